// round 10
// baseline (speedup 1.0000x reference)
#include <cuda_runtime.h>
#include <cuda_bf16.h>
#include <cstdint>

// Problem constants
#define TT      524288
#define INLEN   64
#define NMEM    64
#define HID     128       // 2*NMEM
#define OUTLEN  32
#define CHUNK   64
#define NCH     (TT / CHUNK)   // 8192

// Scratch (device globals — allocation-free rule)
__device__ float2 g_ab[TT * NMEM];      // interleaved (a,b) pairs: 268 MB
__device__ float g_cA[NMEM * NCH];      // per-chunk composed A, CHANNEL-MAJOR [ch][c]
__device__ float g_cB[NMEM * NCH];      // per-chunk composed B, CHANNEL-MAJOR [ch][c]
__device__ float g_qA[NCH * 4 * NMEM];  // per-quarter aggregates [c][q][ch]
__device__ float g_qB[NCH * 4 * NMEM];
__device__ float g_pB[NCH * NMEM];      // exclusive-prefix B = z at chunk start [c][ch]
__device__ __align__(16) uint8_t g_W1t[36864];  // W1^T bf16 tiles: hi[128][72] then lo

// ===================== helpers =====================
__device__ __forceinline__ uint32_t smem_u32(const void* p) {
    uint32_t a;
    asm("{ .reg .u64 t; cvta.to.shared.u64 t, %1; cvt.u32.u64 %0, t; }" : "=r"(a) : "l"(p));
    return a;
}
__device__ __forceinline__ float sigmoidf_(float x) {
    return __fdividef(1.0f, 1.0f + __expf(-x));
}
// base-target tensor path (valid on plain sm_103)
__device__ __forceinline__ void ldsm_x4(uint32_t* r, uint32_t a) {
    asm volatile("ldmatrix.sync.aligned.m8n8.x4.shared.b16 {%0,%1,%2,%3}, [%4];"
                 : "=r"(r[0]), "=r"(r[1]), "=r"(r[2]), "=r"(r[3]) : "r"(a));
}
__device__ __forceinline__ void mma16816(float* c, const uint32_t* a,
                                         uint32_t b0, uint32_t b1) {
    asm volatile("mma.sync.aligned.m16n8k16.row.col.f32.bf16.bf16.f32 "
                 "{%0,%1,%2,%3}, {%4,%5,%6,%7}, {%8,%9}, {%0,%1,%2,%3};"
                 : "+f"(c[0]), "+f"(c[1]), "+f"(c[2]), "+f"(c[3])
                 : "r"(a[0]), "r"(a[1]), "r"(a[2]), "r"(a[3]), "r"(b0), "r"(b1));
}
// bf16 hi/lo split of two floats, packed as bf16x2 words
__device__ __forceinline__ void bfsplit2(float x, float y, uint32_t& hi, uint32_t& lo) {
    __nv_bfloat16 hx = __float2bfloat16_rn(x);
    __nv_bfloat16 hy = __float2bfloat16_rn(y);
    __nv_bfloat16 lx = __float2bfloat16_rn(x - __bfloat162float(hx));
    __nv_bfloat16 ly = __float2bfloat16_rn(y - __bfloat162float(hy));
    hi = (uint32_t)__bfloat16_as_ushort(hx) | ((uint32_t)__bfloat16_as_ushort(hy) << 16);
    lo = (uint32_t)__bfloat16_as_ushort(lx) | ((uint32_t)__bfloat16_as_ushort(ly) << 16);
}

// SMEM layout (byte offsets from 1024-aligned base). Tile rows padded to
// 72 bf16 = 144 B so ldmatrix row addresses hit distinct banks.
#define TSTRIDE 144
#define OFF_AH  0            // x hi  [64 m][72 k] bf16 : 9216 B
#define OFF_AL  9216         // x lo
#define OFF_BH  18432        // W1^T hi [128 n][72 k] bf16 : 18432 B
#define OFF_BL  36864        //           ... ends at 55296
#define OFF_HS  0            // f32 [64][132] = 33792 B, OVERLAYS tiles (post-MMA)
#define HS_ST   132
#define P1_DSMEM (55296 + 1024)

// =====================================================================
// Pre-kernel: convert W1 -> bf16 hi/lo tile image (exact smem layout).
// =====================================================================
__global__ __launch_bounds__(512) void convW1_kernel(const float* __restrict__ W1) {
    const int tid = threadIdx.x;
#pragma unroll
    for (int it = 0; it < 16; it++) {
        int i = it * 512 + tid;          // k = i>>7, n = i&127 (coalesced read)
        int k = i >> 7, n = i & 127;
        float v = W1[i];
        __nv_bfloat16 h = __float2bfloat16_rn(v);
        __nv_bfloat16 l = __float2bfloat16_rn(v - __bfloat162float(h));
        uint32_t off = n * TSTRIDE + k * 2;
        *(__nv_bfloat16*)(g_W1t + off)         = h;
        *(__nv_bfloat16*)(g_W1t + 18432 + off) = l;
    }
}

// =====================================================================
// GEMM1 via mma.sync bf16-split: 64-row chunk, 256 threads = 8 warps,
// warp = (m-tile 0..3, n-half 0..1). Writes Hs = sigmoid(x@W1+B1).
// =====================================================================
__device__ __forceinline__ void gemm1_hs(
    const float* __restrict__ xblk, const float* __restrict__ B1,
    char* base_c, uint32_t base_u, float* b1s, int tid) {

    char* Ah = base_c + OFF_AH;
    char* Al = base_c + OFF_AL;

    // ---- A tiles: x chunk [64 m][64 k] f32 -> bf16 hi/lo ----
#pragma unroll
    for (int it = 0; it < 4; it++) {
        int i = it * 256 + tid;          // float4 idx: row = i>>4, kq = i&15
        int row = i >> 4, kq = i & 15;
        float4 v = ((const float4*)xblk)[i];
        uint2 ph, pl;
        bfsplit2(v.x, v.y, ph.x, pl.x);
        bfsplit2(v.z, v.w, ph.y, pl.y);
        uint32_t off = row * TSTRIDE + kq * 8;
        *(uint2*)(Ah + off) = ph;
        *(uint2*)(Al + off) = pl;
    }
    // ---- B tiles: straight copy of pre-converted image (L2-hot) ----
#pragma unroll
    for (int it = 0; it < 9; it++) {
        int i = it * 256 + tid;          // 2304 uint4 = 36864 B
        ((uint4*)(base_c + OFF_BH))[i] = ((const uint4*)g_W1t)[i];
    }
    if (tid < HID) b1s[tid] = B1[tid];
    __syncthreads();

    const int wid  = tid >> 5, lane = tid & 31;
    const int mw   = wid & 3;      // m-tile: rows 16*mw..+15
    const int nh   = wid >> 2;     // n-half: n-tiles 8*nh..+7

    // ---- preload A fragments for 4 k-steps, hi+lo ----
    uint32_t AhF[4][4], AlF[4][4];
    {
        uint32_t arow  = mw * 16 + (lane & 15);
        uint32_t acol8 = (lane >> 4) << 3;     // 0 or 8
#pragma unroll
        for (int kk = 0; kk < 4; kk++) {
            uint32_t ad = base_u + OFF_AH + arow * TSTRIDE + (kk * 16 + acol8) * 2;
            ldsm_x4(AhF[kk], ad);
            ldsm_x4(AlF[kk], ad + (OFF_AL - OFF_AH));
        }
    }

    float acc[8][4];
#pragma unroll
    for (int j = 0; j < 8; j++)
#pragma unroll
        for (int q = 0; q < 4; q++) acc[j][q] = 0.0f;

    const uint32_t brow7 = lane & 7;
    const uint32_t bcol8 = (lane >> 3) << 3;   // 0,8,16,24 -> k offsets in 32-block
#pragma unroll
    for (int j = 0; j < 8; j++) {
        int jn = nh * 8 + j;                   // global n-tile
#pragma unroll
        for (int kk2 = 0; kk2 < 2; kk2++) {    // k 0-31, 32-63
            uint32_t bd = base_u + OFF_BH + (8 * jn + brow7) * TSTRIDE
                        + (kk2 * 32 + bcol8) * 2;
            uint32_t Bhf[4], Blf[4];
            ldsm_x4(Bhf, bd);
            ldsm_x4(Blf, bd + (OFF_BL - OFF_BH));
#pragma unroll
            for (int sh = 0; sh < 2; sh++) {
                int s = kk2 * 2 + sh;
                mma16816(acc[j], AhF[s], Bhf[sh * 2], Bhf[sh * 2 + 1]);  // xh*Wh
                mma16816(acc[j], AhF[s], Blf[sh * 2], Blf[sh * 2 + 1]);  // xh*Wl
                mma16816(acc[j], AlF[s], Bhf[sh * 2], Bhf[sh * 2 + 1]);  // xl*Wh
            }
        }
    }
    __syncthreads();   // all MMAs done -> bf16 tiles dead, Hs overlay safe

    // ---- epilogue: bias + sigmoid -> Hs ----
    float* Hs = (float*)(base_c + OFF_HS);
    {
        int r0 = mw * 16 + (lane >> 2);
        int c0 = (lane & 3) * 2;
#pragma unroll
        for (int j = 0; j < 8; j++) {
            int n = 8 * (nh * 8 + j) + c0;
            Hs[r0 * HS_ST + n]           = sigmoidf_(acc[j][0] + b1s[n]);
            Hs[r0 * HS_ST + n + 1]       = sigmoidf_(acc[j][1] + b1s[n + 1]);
            Hs[(r0 + 8) * HS_ST + n]     = sigmoidf_(acc[j][2] + b1s[n]);
            Hs[(r0 + 8) * HS_ST + n + 1] = sigmoidf_(acc[j][3] + b1s[n + 1]);
        }
    }
    __syncthreads();
}

// =====================================================================
// Phase 1: tensor GEMM1 -> Hs; write (a,b) float2 + quarter aggregates;
// chunk aggregates. 256 threads, 2 CTAs/SM.
// =====================================================================
__global__ __launch_bounds__(256, 2) void phase1_kernel(
    const float* __restrict__ x, const float* __restrict__ B1) {
    extern __shared__ char dyn[];
    __shared__ float b1s[HID];
    __shared__ float QA[4 * NMEM], QB[4 * NMEM];

    const int tid = threadIdx.x;
    const int c   = blockIdx.x;
    uint32_t du = smem_u32(dyn);
    uint32_t bu = (du + 1023u) & ~1023u;
    char* base_c = dyn + (bu - du);
    float* Hs = (float*)(base_c + OFF_HS);

    gemm1_hs(x + (size_t)c * CHUNK * INLEN, B1, base_c, bu, b1s, tid);

    // write (a,b) interleaved float2 (coalesced 256B/warp): layout [T][64]
    const size_t gbase = (size_t)c * CHUNK * NMEM;
#pragma unroll 4
    for (int i = tid; i < CHUNK * NMEM; i += 256) {
        int t = i >> 6, ch = i & 63;
        float l = Hs[t * HS_ST + ch];
        float r = Hs[t * HS_ST + ch + 64];
        g_ab[gbase + i] = make_float2(l * r, 1.0f - l);
    }

    // compose: 4 segments of 16 rows per channel (exactly 256 threads)
    const int ch = tid & 63, q = tid >> 6;
    {
        float A = 1.0f, Bv = 0.0f;
#pragma unroll
        for (int t = 0; t < 16; t++) {
            int row = q * 16 + t;
            float l = Hs[row * HS_ST + ch];
            float r = Hs[row * HS_ST + ch + 64];
            float a = l * r, b = 1.0f - l;
            Bv = a * Bv + b;
            A *= a;
        }
        QA[q * NMEM + ch] = A;
        QB[q * NMEM + ch] = Bv;
        // persist quarter aggregates for phase3 ([c][q][ch] = [c*256 + tid])
        g_qA[(size_t)c * 256 + tid] = A;
        g_qB[(size_t)c * 256 + tid] = Bv;
    }
    __syncthreads();
    if (tid < NMEM) {
        float A = 1.0f, Bv = 0.0f;
#pragma unroll
        for (int qq = 0; qq < 4; qq++) {
            float a = QA[qq * NMEM + tid], b = QB[qq * NMEM + tid];
            Bv = a * Bv + b;
            A *= a;
        }
        g_cA[tid * NCH + c] = A;    // channel-major for phase2
        g_cB[tid * NCH + c] = Bv;
    }
}

// =====================================================================
// Phase 2: hierarchical exclusive scan over 8192 chunk compositions.
// 64 blocks (one per channel), 256 threads, 32 chunks per thread.
// =====================================================================
#define P2_DSMEM (2 * NCH * 4)
__global__ __launch_bounds__(256) void phase2_kernel() {
    extern __shared__ float p2sm[];
    float* cAs = p2sm;           // [8192]
    float* cBs = p2sm + NCH;     // [8192]
    __shared__ float SA[256], SB[256];
    const int ch  = blockIdx.x;
    const int tid = threadIdx.x;

    for (int i = tid; i < NCH / 4; i += 256) {
        ((float4*)cAs)[i] = ((const float4*)(g_cA + (size_t)ch * NCH))[i];
        ((float4*)cBs)[i] = ((const float4*)(g_cB + (size_t)ch * NCH))[i];
    }
    __syncthreads();

    const int base = tid * 32;
    float A = 1.0f, Bv = 0.0f;
#pragma unroll
    for (int j = 0; j < 32; j++) {
        float a = cAs[base + j], b = cBs[base + j];
        Bv = a * Bv + b;
        A *= a;
    }
    SA[tid] = A; SB[tid] = Bv;
    __syncthreads();

#pragma unroll
    for (int s = 1; s < 256; s <<= 1) {
        float ta = SA[tid], tb = SB[tid];
        float pa = 1.0f, pb = 0.0f;
        if (tid >= s) { pa = SA[tid - s]; pb = SB[tid - s]; }
        __syncthreads();
        if (tid >= s) { SA[tid] = ta * pa; SB[tid] = ta * pb + tb; }
        __syncthreads();
    }

    float PB = (tid > 0) ? SB[tid - 1] : 0.0f;
#pragma unroll
    for (int j = 0; j < 32; j++) {
        g_pB[(size_t)(base + j) * NMEM + ch] = PB;
        PB = cAs[base + j] * PB + cBs[base + j];
    }
}

// =====================================================================
// Phase 3: load (a,b) float2 + precomputed quarter aggregates; single
// replay pass -> Zs TRANSPOSED [ch][row] (pad 68); GEMM2 with float4
// z-loads on 128 threads (4 rows x 4 cols per thread).
// =====================================================================
#define ZST 68
__global__ __launch_bounds__(256) void phase3_kernel(
    const float* __restrict__ W2, const float* __restrict__ B2,
    float* __restrict__ out) {
    __shared__ float Zs[NMEM * ZST];         // 64 ch x 68  (17408 B)
    __shared__ float W2s[64 * 32];
    __shared__ float QAs[4 * NMEM], QBs[4 * NMEM];
    __shared__ float pBs[NMEM];

    const int tid = threadIdx.x;
    const int c   = blockIdx.x;
    const size_t base = (size_t)c * CHUNK * NMEM;

    for (int i = tid; i < 64 * 32 / 4; i += 256)
        ((float4*)W2s)[i] = ((const float4*)W2)[i];
    if (tid < NMEM) pBs[tid] = g_pB[(size_t)c * NMEM + tid];
    QAs[tid] = g_qA[(size_t)c * 256 + tid];
    QBs[tid] = g_qB[(size_t)c * 256 + tid];

    // load (a,b) for this thread's 16 rows (coalesced float2 = 256B/warp)
    const int ch = tid & 63, q = tid >> 6;
    float2 ab[16];
#pragma unroll
    for (int t = 0; t < 16; t++)
        ab[t] = g_ab[base + (q * 16 + t) * NMEM + ch];
    __syncthreads();

    // starting value from precomputed quarter aggregates, then replay
    {
        float u = pBs[ch];
#pragma unroll
        for (int j = 0; j < 3; j++)
            if (j < q) u = QAs[j * NMEM + ch] * u + QBs[j * NMEM + ch];
#pragma unroll
        for (int t = 0; t < 16; t++) {
            Zs[ch * ZST + (q * 16 + t)] = u;   // transposed
            u = ab[t].x * u + ab[t].y;
        }
    }
    __syncthreads();

    // GEMM2: out[64][32] = Zs^T @ W2s + B2. 128 threads, tile 4 rows x 4 cols.
    if (tid < 128) {
        const int colg = (tid & 7) * 4;    // 0..28
        const int rowg = (tid >> 3) * 4;   // 0..60
        float acc[4][4];
#pragma unroll
        for (int i = 0; i < 4; i++)
#pragma unroll
            for (int j = 0; j < 4; j++) acc[i][j] = 0.0f;

#pragma unroll 8
        for (int k = 0; k < 64; k++) {
            float4 w = *(const float4*)&W2s[k * 32 + colg];
            float4 z = *(const float4*)&Zs[k * ZST + rowg];
            acc[0][0] += z.x * w.x; acc[0][1] += z.x * w.y; acc[0][2] += z.x * w.z; acc[0][3] += z.x * w.w;
            acc[1][0] += z.y * w.x; acc[1][1] += z.y * w.y; acc[1][2] += z.y * w.z; acc[1][3] += z.y * w.w;
            acc[2][0] += z.z * w.x; acc[2][1] += z.z * w.y; acc[2][2] += z.z * w.z; acc[2][3] += z.z * w.w;
            acc[3][0] += z.w * w.x; acc[3][1] += z.w * w.y; acc[3][2] += z.w * w.z; acc[3][3] += z.w * w.w;
        }

        float b0 = B2[colg + 0], b1 = B2[colg + 1], b2 = B2[colg + 2], b3 = B2[colg + 3];
#pragma unroll
        for (int i = 0; i < 4; i++) {
            float4 o;
            o.x = acc[i][0] + b0;
            o.y = acc[i][1] + b1;
            o.z = acc[i][2] + b2;
            o.w = acc[i][3] + b3;
            size_t row = (size_t)c * CHUNK + rowg + i;
            *(float4*)&out[row * OUTLEN + colg] = o;
        }
    }
}

// =====================================================================
extern "C" void kernel_launch(void* const* d_in, const int* in_sizes, int n_in,
                              void* d_out, int out_size) {
    const float* x  = (const float*)d_in[0];   // [T, 64]
    const float* W1 = (const float*)d_in[1];   // [64, 128]
    const float* B1 = (const float*)d_in[2];   // [1, 128]
    const float* W2 = (const float*)d_in[3];   // [64, 32]
    const float* B2 = (const float*)d_in[4];   // [1, 32]
    float* out = (float*)d_out;                // [T, 32]

    cudaFuncSetAttribute(phase1_kernel, cudaFuncAttributeMaxDynamicSharedMemorySize, P1_DSMEM);
    cudaFuncSetAttribute(phase2_kernel, cudaFuncAttributeMaxDynamicSharedMemorySize, P2_DSMEM);

    convW1_kernel<<<1, 512>>>(W1);
    phase1_kernel<<<NCH, 256, P1_DSMEM>>>(x, B1);
    phase2_kernel<<<64, 256, P2_DSMEM>>>();
    phase3_kernel<<<NCH, 256>>>(W2, B2, out);
}

// round 11
// speedup vs baseline: 1.4929x; 1.4929x over previous
#include <cuda_runtime.h>
#include <cuda_bf16.h>
#include <cstdint>

// Problem constants
#define TT      524288
#define INLEN   64
#define NMEM    64
#define HID     128       // 2*NMEM
#define OUTLEN  32
#define CHUNK   64
#define NCH     (TT / CHUNK)   // 8192

// Scratch (device globals — allocation-free rule)
__device__ float g_a[TT * NMEM];        // 134 MB
__device__ float g_b[TT * NMEM];        // 134 MB
__device__ float g_cA[NMEM * NCH];      // per-chunk composed A, CHANNEL-MAJOR [ch][c]
__device__ float g_cB[NMEM * NCH];      // per-chunk composed B, CHANNEL-MAJOR [ch][c]
__device__ float g_qA[NCH * 4 * NMEM];  // per-quarter aggregates [c][q][ch]
__device__ float g_qB[NCH * 4 * NMEM];
__device__ float g_pB[NCH * NMEM];      // exclusive-prefix B = z at chunk start [c][ch]
__device__ __align__(16) uint8_t g_W1t[36864];  // W1^T bf16 tiles: hi[128][72] then lo

// ===================== helpers =====================
__device__ __forceinline__ uint32_t smem_u32(const void* p) {
    uint32_t a;
    asm("{ .reg .u64 t; cvta.to.shared.u64 t, %1; cvt.u32.u64 %0, t; }" : "=r"(a) : "l"(p));
    return a;
}
__device__ __forceinline__ float sigmoidf_(float x) {
    return __fdividef(1.0f, 1.0f + __expf(-x));
}
// base-target tensor path (valid on plain sm_103)
__device__ __forceinline__ void ldsm_x4(uint32_t* r, uint32_t a) {
    asm volatile("ldmatrix.sync.aligned.m8n8.x4.shared.b16 {%0,%1,%2,%3}, [%4];"
                 : "=r"(r[0]), "=r"(r[1]), "=r"(r[2]), "=r"(r[3]) : "r"(a));
}
__device__ __forceinline__ void mma16816(float* c, const uint32_t* a,
                                         uint32_t b0, uint32_t b1) {
    asm volatile("mma.sync.aligned.m16n8k16.row.col.f32.bf16.bf16.f32 "
                 "{%0,%1,%2,%3}, {%4,%5,%6,%7}, {%8,%9}, {%0,%1,%2,%3};"
                 : "+f"(c[0]), "+f"(c[1]), "+f"(c[2]), "+f"(c[3])
                 : "r"(a[0]), "r"(a[1]), "r"(a[2]), "r"(a[3]), "r"(b0), "r"(b1));
}
// bf16 hi/lo split of two floats, packed as bf16x2 words
__device__ __forceinline__ void bfsplit2(float x, float y, uint32_t& hi, uint32_t& lo) {
    __nv_bfloat16 hx = __float2bfloat16_rn(x);
    __nv_bfloat16 hy = __float2bfloat16_rn(y);
    __nv_bfloat16 lx = __float2bfloat16_rn(x - __bfloat162float(hx));
    __nv_bfloat16 ly = __float2bfloat16_rn(y - __bfloat162float(hy));
    hi = (uint32_t)__bfloat16_as_ushort(hx) | ((uint32_t)__bfloat16_as_ushort(hy) << 16);
    lo = (uint32_t)__bfloat16_as_ushort(lx) | ((uint32_t)__bfloat16_as_ushort(ly) << 16);
}

// SMEM layout (byte offsets from 1024-aligned base). Tile rows padded to
// 72 bf16 = 144 B so ldmatrix row addresses hit distinct banks.
#define TSTRIDE 144
#define OFF_AH  0            // x hi  [64 m][72 k] bf16 : 9216 B
#define OFF_AL  9216         // x lo
#define OFF_BH  18432        // W1^T hi [128 n][72 k] bf16 : 18432 B
#define OFF_BL  36864        //           ... ends at 55296
#define OFF_HS  0            // f32 [64][132] = 33792 B, OVERLAYS tiles (post-MMA)
#define HS_ST   132
#define P1_DSMEM (55296 + 1024)

// =====================================================================
// Pre-kernel: convert W1 -> bf16 hi/lo tile image (exact smem layout).
// =====================================================================
__global__ __launch_bounds__(512) void convW1_kernel(const float* __restrict__ W1) {
    const int tid = threadIdx.x;
#pragma unroll
    for (int it = 0; it < 16; it++) {
        int i = it * 512 + tid;          // k = i>>7, n = i&127 (coalesced read)
        int k = i >> 7, n = i & 127;
        float v = W1[i];
        __nv_bfloat16 h = __float2bfloat16_rn(v);
        __nv_bfloat16 l = __float2bfloat16_rn(v - __bfloat162float(h));
        uint32_t off = n * TSTRIDE + k * 2;
        *(__nv_bfloat16*)(g_W1t + off)         = h;
        *(__nv_bfloat16*)(g_W1t + 18432 + off) = l;
    }
}

// =====================================================================
// GEMM1 via mma.sync bf16-split: 64-row chunk, 256 threads = 8 warps,
// warp = (m-tile 0..3, n-half 0..1). Writes Hs = sigmoid(x@W1+B1).
// =====================================================================
__device__ __forceinline__ void gemm1_hs(
    const float* __restrict__ xblk, const float* __restrict__ B1,
    char* base_c, uint32_t base_u, float* b1s, int tid) {

    char* Ah = base_c + OFF_AH;
    char* Al = base_c + OFF_AL;

    // ---- A tiles: x chunk [64 m][64 k] f32 -> bf16 hi/lo ----
#pragma unroll
    for (int it = 0; it < 4; it++) {
        int i = it * 256 + tid;          // float4 idx: row = i>>4, kq = i&15
        int row = i >> 4, kq = i & 15;
        float4 v = ((const float4*)xblk)[i];
        uint2 ph, pl;
        bfsplit2(v.x, v.y, ph.x, pl.x);
        bfsplit2(v.z, v.w, ph.y, pl.y);
        uint32_t off = row * TSTRIDE + kq * 8;
        *(uint2*)(Ah + off) = ph;
        *(uint2*)(Al + off) = pl;
    }
    // ---- B tiles: straight copy of pre-converted image (L2-hot) ----
#pragma unroll
    for (int it = 0; it < 9; it++) {
        int i = it * 256 + tid;          // 2304 uint4 = 36864 B
        ((uint4*)(base_c + OFF_BH))[i] = ((const uint4*)g_W1t)[i];
    }
    if (tid < HID) b1s[tid] = B1[tid];
    __syncthreads();

    const int wid  = tid >> 5, lane = tid & 31;
    const int mw   = wid & 3;      // m-tile: rows 16*mw..+15
    const int nh   = wid >> 2;     // n-half: n-tiles 8*nh..+7

    // ---- preload A fragments for 4 k-steps, hi+lo ----
    uint32_t AhF[4][4], AlF[4][4];
    {
        uint32_t arow  = mw * 16 + (lane & 15);
        uint32_t acol8 = (lane >> 4) << 3;     // 0 or 8
#pragma unroll
        for (int kk = 0; kk < 4; kk++) {
            uint32_t ad = base_u + OFF_AH + arow * TSTRIDE + (kk * 16 + acol8) * 2;
            ldsm_x4(AhF[kk], ad);
            ldsm_x4(AlF[kk], ad + (OFF_AL - OFF_AH));
        }
    }

    float acc[8][4];
#pragma unroll
    for (int j = 0; j < 8; j++)
#pragma unroll
        for (int q = 0; q < 4; q++) acc[j][q] = 0.0f;

    const uint32_t brow7 = lane & 7;
    const uint32_t bcol8 = (lane >> 3) << 3;   // 0,8,16,24 -> k offsets in 32-block
#pragma unroll
    for (int j = 0; j < 8; j++) {
        int jn = nh * 8 + j;                   // global n-tile
#pragma unroll
        for (int kk2 = 0; kk2 < 2; kk2++) {    // k 0-31, 32-63
            uint32_t bd = base_u + OFF_BH + (8 * jn + brow7) * TSTRIDE
                        + (kk2 * 32 + bcol8) * 2;
            uint32_t Bhf[4], Blf[4];
            ldsm_x4(Bhf, bd);
            ldsm_x4(Blf, bd + (OFF_BL - OFF_BH));
#pragma unroll
            for (int sh = 0; sh < 2; sh++) {
                int s = kk2 * 2 + sh;
                mma16816(acc[j], AhF[s], Bhf[sh * 2], Bhf[sh * 2 + 1]);  // xh*Wh
                mma16816(acc[j], AhF[s], Blf[sh * 2], Blf[sh * 2 + 1]);  // xh*Wl
                mma16816(acc[j], AlF[s], Bhf[sh * 2], Bhf[sh * 2 + 1]);  // xl*Wh
            }
        }
    }
    __syncthreads();   // all MMAs done -> bf16 tiles dead, Hs overlay safe

    // ---- epilogue: bias + sigmoid -> Hs ----
    float* Hs = (float*)(base_c + OFF_HS);
    {
        int r0 = mw * 16 + (lane >> 2);
        int c0 = (lane & 3) * 2;
#pragma unroll
        for (int j = 0; j < 8; j++) {
            int n = 8 * (nh * 8 + j) + c0;
            Hs[r0 * HS_ST + n]           = sigmoidf_(acc[j][0] + b1s[n]);
            Hs[r0 * HS_ST + n + 1]       = sigmoidf_(acc[j][1] + b1s[n + 1]);
            Hs[(r0 + 8) * HS_ST + n]     = sigmoidf_(acc[j][2] + b1s[n]);
            Hs[(r0 + 8) * HS_ST + n + 1] = sigmoidf_(acc[j][3] + b1s[n + 1]);
        }
    }
    __syncthreads();
}

// =====================================================================
// Phase 1: tensor GEMM1 -> Hs; write a,b to gmem + quarter aggregates;
// chunk aggregates. 256 threads, 2 CTAs/SM.
// =====================================================================
__global__ __launch_bounds__(256, 2) void phase1_kernel(
    const float* __restrict__ x, const float* __restrict__ B1) {
    extern __shared__ char dyn[];
    __shared__ float b1s[HID];
    __shared__ float QA[4 * NMEM], QB[4 * NMEM];

    const int tid = threadIdx.x;
    const int c   = blockIdx.x;
    uint32_t du = smem_u32(dyn);
    uint32_t bu = (du + 1023u) & ~1023u;
    char* base_c = dyn + (bu - du);
    float* Hs = (float*)(base_c + OFF_HS);

    gemm1_hs(x + (size_t)c * CHUNK * INLEN, B1, base_c, bu, b1s, tid);

    // write a,b to gmem (coalesced): layout [T][64]
    const size_t gbase = (size_t)c * CHUNK * NMEM;
#pragma unroll 4
    for (int i = tid; i < CHUNK * NMEM; i += 256) {
        int t = i >> 6, ch = i & 63;
        float l = Hs[t * HS_ST + ch];
        float r = Hs[t * HS_ST + ch + 64];
        g_a[gbase + i] = l * r;
        g_b[gbase + i] = 1.0f - l;
    }

    // compose: 4 segments of 16 rows per channel (exactly 256 threads)
    const int ch = tid & 63, q = tid >> 6;
    {
        float A = 1.0f, Bv = 0.0f;
#pragma unroll
        for (int t = 0; t < 16; t++) {
            int row = q * 16 + t;
            float l = Hs[row * HS_ST + ch];
            float r = Hs[row * HS_ST + ch + 64];
            float a = l * r, b = 1.0f - l;
            Bv = a * Bv + b;
            A *= a;
        }
        QA[q * NMEM + ch] = A;
        QB[q * NMEM + ch] = Bv;
        // persist quarter aggregates for phase3 ([c][q][ch] = [c*256 + tid])
        g_qA[(size_t)c * 256 + tid] = A;
        g_qB[(size_t)c * 256 + tid] = Bv;
    }
    __syncthreads();
    if (tid < NMEM) {
        float A = 1.0f, Bv = 0.0f;
#pragma unroll
        for (int qq = 0; qq < 4; qq++) {
            float a = QA[qq * NMEM + tid], b = QB[qq * NMEM + tid];
            Bv = a * Bv + b;
            A *= a;
        }
        g_cA[tid * NCH + c] = A;    // channel-major for phase2
        g_cB[tid * NCH + c] = Bv;
    }
}

// =====================================================================
// Phase 2: hierarchical exclusive scan over 8192 chunk compositions.
// 64 blocks (one per channel), 256 threads, 32 chunks per thread.
// =====================================================================
#define P2_DSMEM (2 * NCH * 4)
__global__ __launch_bounds__(256) void phase2_kernel() {
    extern __shared__ float p2sm[];
    float* cAs = p2sm;           // [8192]
    float* cBs = p2sm + NCH;     // [8192]
    __shared__ float SA[256], SB[256];
    const int ch  = blockIdx.x;
    const int tid = threadIdx.x;

    for (int i = tid; i < NCH / 4; i += 256) {
        ((float4*)cAs)[i] = ((const float4*)(g_cA + (size_t)ch * NCH))[i];
        ((float4*)cBs)[i] = ((const float4*)(g_cB + (size_t)ch * NCH))[i];
    }
    __syncthreads();

    const int base = tid * 32;
    float A = 1.0f, Bv = 0.0f;
#pragma unroll
    for (int j = 0; j < 32; j++) {
        float a = cAs[base + j], b = cBs[base + j];
        Bv = a * Bv + b;
        A *= a;
    }
    SA[tid] = A; SB[tid] = Bv;
    __syncthreads();

#pragma unroll
    for (int s = 1; s < 256; s <<= 1) {
        float ta = SA[tid], tb = SB[tid];
        float pa = 1.0f, pb = 0.0f;
        if (tid >= s) { pa = SA[tid - s]; pb = SB[tid - s]; }
        __syncthreads();
        if (tid >= s) { SA[tid] = ta * pa; SB[tid] = ta * pb + tb; }
        __syncthreads();
    }

    float PB = (tid > 0) ? SB[tid - 1] : 0.0f;
#pragma unroll
    for (int j = 0; j < 32; j++) {
        g_pB[(size_t)(base + j) * NMEM + ch] = PB;
        PB = cAs[base + j] * PB + cBs[base + j];
    }
}

// =====================================================================
// Phase 3 (R9-proven form + precomputed aggregates): a,b in registers;
// single replay pass -> Zs[row][ch] (pad 65); GEMM2 2 rows x 4 cols.
// 256 threads: thread = (ch 0..63, q 0..3), 16 rows each.
// =====================================================================
#define ZPAD 65
__global__ __launch_bounds__(256) void phase3_kernel(
    const float* __restrict__ W2, const float* __restrict__ B2,
    float* __restrict__ out) {
    __shared__ float Zs[CHUNK * ZPAD];       // 64*65
    __shared__ float W2s[64 * 32];
    __shared__ float QAs[4 * NMEM], QBs[4 * NMEM];
    __shared__ float pBs[NMEM];

    const int tid = threadIdx.x;
    const int c   = blockIdx.x;
    const size_t base = (size_t)c * CHUNK * NMEM;

    for (int i = tid; i < 64 * 32 / 4; i += 256)
        ((float4*)W2s)[i] = ((const float4*)W2)[i];
    if (tid < NMEM) pBs[tid] = g_pB[(size_t)c * NMEM + tid];
    QAs[tid] = g_qA[(size_t)c * 256 + tid];
    QBs[tid] = g_qB[(size_t)c * 256 + tid];

    // load a,b for this thread's 16 rows into registers (coalesced)
    const int ch = tid & 63, q = tid >> 6;
    float ar[16], br[16];
#pragma unroll
    for (int t = 0; t < 16; t++) {
        int row = q * 16 + t;
        ar[t] = g_a[base + row * NMEM + ch];
        br[t] = g_b[base + row * NMEM + ch];
    }
    __syncthreads();

    // starting value from precomputed quarter aggregates, then replay
    {
        float u = pBs[ch];
#pragma unroll
        for (int j = 0; j < 3; j++)
            if (j < q) u = QAs[j * NMEM + ch] * u + QBs[j * NMEM + ch];
#pragma unroll
        for (int t = 0; t < 16; t++) {
            int row = q * 16 + t;
            Zs[row * ZPAD + ch] = u;
            u = ar[t] * u + br[t];
        }
    }
    __syncthreads();

    // GEMM2: Zs[64][64] @ W2s[64][32]. Thread tile 2 rows x 4 cols.
    const int colg = (tid & 7) * 4;    // 0..28
    const int rowg = (tid >> 3) * 2;   // 0..62
    float acc[2][4];
#pragma unroll
    for (int i = 0; i < 2; i++)
#pragma unroll
        for (int j = 0; j < 4; j++) acc[i][j] = 0.0f;

#pragma unroll 8
    for (int k = 0; k < 64; k++) {
        float4 w = *(const float4*)&W2s[k * 32 + colg];
        float z0 = Zs[(rowg + 0) * ZPAD + k];
        float z1 = Zs[(rowg + 1) * ZPAD + k];
        acc[0][0] += z0 * w.x; acc[0][1] += z0 * w.y; acc[0][2] += z0 * w.z; acc[0][3] += z0 * w.w;
        acc[1][0] += z1 * w.x; acc[1][1] += z1 * w.y; acc[1][2] += z1 * w.z; acc[1][3] += z1 * w.w;
    }

    float b0 = B2[colg + 0], b1 = B2[colg + 1], b2 = B2[colg + 2], b3 = B2[colg + 3];
#pragma unroll
    for (int i = 0; i < 2; i++) {
        float4 o;
        o.x = acc[i][0] + b0;
        o.y = acc[i][1] + b1;
        o.z = acc[i][2] + b2;
        o.w = acc[i][3] + b3;
        size_t row = (size_t)c * CHUNK + rowg + i;
        *(float4*)&out[row * OUTLEN + colg] = o;
    }
}

// =====================================================================
extern "C" void kernel_launch(void* const* d_in, const int* in_sizes, int n_in,
                              void* d_out, int out_size) {
    const float* x  = (const float*)d_in[0];   // [T, 64]
    const float* W1 = (const float*)d_in[1];   // [64, 128]
    const float* B1 = (const float*)d_in[2];   // [1, 128]
    const float* W2 = (const float*)d_in[3];   // [64, 32]
    const float* B2 = (const float*)d_in[4];   // [1, 32]
    float* out = (float*)d_out;                // [T, 32]

    cudaFuncSetAttribute(phase1_kernel, cudaFuncAttributeMaxDynamicSharedMemorySize, P1_DSMEM);
    cudaFuncSetAttribute(phase2_kernel, cudaFuncAttributeMaxDynamicSharedMemorySize, P2_DSMEM);

    convW1_kernel<<<1, 512>>>(W1);
    phase1_kernel<<<NCH, 256, P1_DSMEM>>>(x, B1);
    phase2_kernel<<<64, 256, P2_DSMEM>>>();
    phase3_kernel<<<NCH, 256>>>(W2, B2, out);
}

// round 14
// speedup vs baseline: 1.7093x; 1.1449x over previous
#include <cuda_runtime.h>
#include <cuda_bf16.h>
#include <cstdint>

// Problem constants
#define TT      524288
#define INLEN   64
#define NMEM    64
#define HID     128       // 2*NMEM
#define OUTLEN  32
#define CHUNK   64
#define NCH     (TT / CHUNK)   // 8192

// Scratch (device globals — allocation-free rule)
__device__ float g_a[TT * NMEM];        // 134 MB
__device__ float g_b[TT * NMEM];        // 134 MB
__device__ float g_cA[NMEM * NCH];      // per-chunk composed A, CHANNEL-MAJOR [ch][c]
__device__ float g_cB[NMEM * NCH];      // per-chunk composed B, CHANNEL-MAJOR [ch][c]
__device__ float g_qA[NCH * 4 * NMEM];  // per-quarter aggregates [c][q][ch]
__device__ float g_qB[NCH * 4 * NMEM];
__device__ float g_pB[NCH * NMEM];      // exclusive-prefix B = z at chunk start [c][ch]
__device__ __align__(16) uint8_t g_W1t[36864];  // W1^T bf16 tiles: hi[128][72] then lo
__device__ __align__(16) uint8_t g_W2t[9216];   // W2^T bf16 tiles: hi[32][72] then lo

// ===================== helpers =====================
__device__ __forceinline__ uint32_t smem_u32(const void* p) {
    uint32_t a;
    asm("{ .reg .u64 t; cvta.to.shared.u64 t, %1; cvt.u32.u64 %0, t; }" : "=r"(a) : "l"(p));
    return a;
}
__device__ __forceinline__ float sigmoidf_(float x) {
    return __fdividef(1.0f, 1.0f + __expf(-x));
}
// base-target tensor path (valid on plain sm_103)
__device__ __forceinline__ void ldsm_x4(uint32_t* r, uint32_t a) {
    asm volatile("ldmatrix.sync.aligned.m8n8.x4.shared.b16 {%0,%1,%2,%3}, [%4];"
                 : "=r"(r[0]), "=r"(r[1]), "=r"(r[2]), "=r"(r[3]) : "r"(a));
}
__device__ __forceinline__ void mma16816(float* c, const uint32_t* a,
                                         uint32_t b0, uint32_t b1) {
    asm volatile("mma.sync.aligned.m16n8k16.row.col.f32.bf16.bf16.f32 "
                 "{%0,%1,%2,%3}, {%4,%5,%6,%7}, {%8,%9}, {%0,%1,%2,%3};"
                 : "+f"(c[0]), "+f"(c[1]), "+f"(c[2]), "+f"(c[3])
                 : "r"(a[0]), "r"(a[1]), "r"(a[2]), "r"(a[3]), "r"(b0), "r"(b1));
}
// bf16 hi/lo split of two floats, packed as bf16x2 words
__device__ __forceinline__ void bfsplit2(float x, float y, uint32_t& hi, uint32_t& lo) {
    __nv_bfloat16 hx = __float2bfloat16_rn(x);
    __nv_bfloat16 hy = __float2bfloat16_rn(y);
    __nv_bfloat16 lx = __float2bfloat16_rn(x - __bfloat162float(hx));
    __nv_bfloat16 ly = __float2bfloat16_rn(y - __bfloat162float(hy));
    hi = (uint32_t)__bfloat16_as_ushort(hx) | ((uint32_t)__bfloat16_as_ushort(hy) << 16);
    lo = (uint32_t)__bfloat16_as_ushort(lx) | ((uint32_t)__bfloat16_as_ushort(ly) << 16);
}
__device__ __forceinline__ void bfsplit1(float x, __nv_bfloat16& h, __nv_bfloat16& l) {
    h = __float2bfloat16_rn(x);
    l = __float2bfloat16_rn(x - __bfloat162float(h));
}

// SMEM layout (byte offsets from 1024-aligned base). Tile rows padded to
// 72 bf16 = 144 B so ldmatrix row addresses hit distinct banks.
#define TSTRIDE 144
#define OFF_AH  0            // x hi  [64 m][72 k] bf16 : 9216 B
#define OFF_AL  9216         // x lo
#define OFF_BH  18432        // W1^T hi [128 n][72 k] bf16 : 18432 B
#define OFF_BL  36864        //           ... ends at 55296
#define OFF_HS  0            // f32 [64][132] = 33792 B, OVERLAYS tiles (post-MMA)
#define HS_ST   132
#define P1_DSMEM (55296 + 1024)

// =====================================================================
// Pre-kernel: convert W1 and W2 -> bf16 hi/lo tile images.
// =====================================================================
__global__ __launch_bounds__(512) void convW_kernel(
    const float* __restrict__ W1, const float* __restrict__ W2) {
    const int tid = threadIdx.x;
#pragma unroll
    for (int it = 0; it < 16; it++) {
        int i = it * 512 + tid;          // k = i>>7, n = i&127 (coalesced read)
        int k = i >> 7, n = i & 127;
        float v = W1[i];
        __nv_bfloat16 h, l;
        bfsplit1(v, h, l);
        uint32_t off = n * TSTRIDE + k * 2;
        *(__nv_bfloat16*)(g_W1t + off)         = h;
        *(__nv_bfloat16*)(g_W1t + 18432 + off) = l;
    }
    // W2 [64 ch][32 col] -> B-tile [32 n=col][72 k=ch] hi/lo
#pragma unroll
    for (int it = 0; it < 4; it++) {
        int i = it * 512 + tid;          // 2048 elements: ch = i>>5, col = i&31
        int ch = i >> 5, col = i & 31;
        float v = W2[i];
        __nv_bfloat16 h, l;
        bfsplit1(v, h, l);
        uint32_t off = col * TSTRIDE + ch * 2;
        *(__nv_bfloat16*)(g_W2t + off)        = h;
        *(__nv_bfloat16*)(g_W2t + 4608 + off) = l;
    }
}

// =====================================================================
// GEMM1 via mma.sync bf16-split: 64-row chunk, 256 threads = 8 warps,
// warp = (m-tile 0..3, n-half 0..1). Writes Hs = sigmoid(x@W1+B1).
// =====================================================================
__device__ __forceinline__ void gemm1_hs(
    const float* __restrict__ xblk, const float* __restrict__ B1,
    char* base_c, uint32_t base_u, float* b1s, int tid) {

    char* Ah = base_c + OFF_AH;
    char* Al = base_c + OFF_AL;

    // ---- A tiles: x chunk [64 m][64 k] f32 -> bf16 hi/lo ----
#pragma unroll
    for (int it = 0; it < 4; it++) {
        int i = it * 256 + tid;          // float4 idx: row = i>>4, kq = i&15
        int row = i >> 4, kq = i & 15;
        float4 v = ((const float4*)xblk)[i];
        uint2 ph, pl;
        bfsplit2(v.x, v.y, ph.x, pl.x);
        bfsplit2(v.z, v.w, ph.y, pl.y);
        uint32_t off = row * TSTRIDE + kq * 8;
        *(uint2*)(Ah + off) = ph;
        *(uint2*)(Al + off) = pl;
    }
    // ---- B tiles: straight copy of pre-converted image (L2-hot) ----
#pragma unroll
    for (int it = 0; it < 9; it++) {
        int i = it * 256 + tid;          // 2304 uint4 = 36864 B
        ((uint4*)(base_c + OFF_BH))[i] = ((const uint4*)g_W1t)[i];
    }
    if (tid < HID) b1s[tid] = B1[tid];
    __syncthreads();

    const int wid  = tid >> 5, lane = tid & 31;
    const int mw   = wid & 3;      // m-tile: rows 16*mw..+15
    const int nh   = wid >> 2;     // n-half: n-tiles 8*nh..+7

    // ---- preload A fragments for 4 k-steps, hi+lo ----
    uint32_t AhF[4][4], AlF[4][4];
    {
        uint32_t arow  = mw * 16 + (lane & 15);
        uint32_t acol8 = (lane >> 4) << 3;     // 0 or 8
#pragma unroll
        for (int kk = 0; kk < 4; kk++) {
            uint32_t ad = base_u + OFF_AH + arow * TSTRIDE + (kk * 16 + acol8) * 2;
            ldsm_x4(AhF[kk], ad);
            ldsm_x4(AlF[kk], ad + (OFF_AL - OFF_AH));
        }
    }

    float acc[8][4];
#pragma unroll
    for (int j = 0; j < 8; j++)
#pragma unroll
        for (int q = 0; q < 4; q++) acc[j][q] = 0.0f;

    const uint32_t brow7 = lane & 7;
    const uint32_t bcol8 = (lane >> 3) << 3;   // 0,8,16,24 -> k offsets in 32-block
#pragma unroll
    for (int j = 0; j < 8; j++) {
        int jn = nh * 8 + j;                   // global n-tile
#pragma unroll
        for (int kk2 = 0; kk2 < 2; kk2++) {    // k 0-31, 32-63
            uint32_t bd = base_u + OFF_BH + (8 * jn + brow7) * TSTRIDE
                        + (kk2 * 32 + bcol8) * 2;
            uint32_t Bhf[4], Blf[4];
            ldsm_x4(Bhf, bd);
            ldsm_x4(Blf, bd + (OFF_BL - OFF_BH));
#pragma unroll
            for (int sh = 0; sh < 2; sh++) {
                int s = kk2 * 2 + sh;
                mma16816(acc[j], AhF[s], Bhf[sh * 2], Bhf[sh * 2 + 1]);  // xh*Wh
                mma16816(acc[j], AhF[s], Blf[sh * 2], Blf[sh * 2 + 1]);  // xh*Wl
                mma16816(acc[j], AlF[s], Bhf[sh * 2], Bhf[sh * 2 + 1]);  // xl*Wh
            }
        }
    }
    __syncthreads();   // all MMAs done -> bf16 tiles dead, Hs overlay safe

    // ---- epilogue: bias + sigmoid -> Hs ----
    float* Hs = (float*)(base_c + OFF_HS);
    {
        int r0 = mw * 16 + (lane >> 2);
        int c0 = (lane & 3) * 2;
#pragma unroll
        for (int j = 0; j < 8; j++) {
            int n = 8 * (nh * 8 + j) + c0;
            Hs[r0 * HS_ST + n]           = sigmoidf_(acc[j][0] + b1s[n]);
            Hs[r0 * HS_ST + n + 1]       = sigmoidf_(acc[j][1] + b1s[n + 1]);
            Hs[(r0 + 8) * HS_ST + n]     = sigmoidf_(acc[j][2] + b1s[n]);
            Hs[(r0 + 8) * HS_ST + n + 1] = sigmoidf_(acc[j][3] + b1s[n + 1]);
        }
    }
    __syncthreads();
}

// =====================================================================
// Phase 1: tensor GEMM1 -> Hs; write a,b to gmem + quarter aggregates;
// chunk aggregates. 256 threads, 2 CTAs/SM.
// =====================================================================
__global__ __launch_bounds__(256, 2) void phase1_kernel(
    const float* __restrict__ x, const float* __restrict__ B1) {
    extern __shared__ char dyn[];
    __shared__ float b1s[HID];
    __shared__ float QA[4 * NMEM], QB[4 * NMEM];

    const int tid = threadIdx.x;
    const int c   = blockIdx.x;
    uint32_t du = smem_u32(dyn);
    uint32_t bu = (du + 1023u) & ~1023u;
    char* base_c = dyn + (bu - du);
    float* Hs = (float*)(base_c + OFF_HS);

    gemm1_hs(x + (size_t)c * CHUNK * INLEN, B1, base_c, bu, b1s, tid);

    // write a,b to gmem (coalesced): layout [T][64]
    const size_t gbase = (size_t)c * CHUNK * NMEM;
#pragma unroll 4
    for (int i = tid; i < CHUNK * NMEM; i += 256) {
        int t = i >> 6, ch = i & 63;
        float l = Hs[t * HS_ST + ch];
        float r = Hs[t * HS_ST + ch + 64];
        g_a[gbase + i] = l * r;
        g_b[gbase + i] = 1.0f - l;
    }

    // compose: 4 segments of 16 rows per channel (exactly 256 threads)
    const int ch = tid & 63, q = tid >> 6;
    {
        float A = 1.0f, Bv = 0.0f;
#pragma unroll
        for (int t = 0; t < 16; t++) {
            int row = q * 16 + t;
            float l = Hs[row * HS_ST + ch];
            float r = Hs[row * HS_ST + ch + 64];
            float a = l * r, b = 1.0f - l;
            Bv = a * Bv + b;
            A *= a;
        }
        QA[q * NMEM + ch] = A;
        QB[q * NMEM + ch] = Bv;
        // persist quarter aggregates for phase3 ([c][q][ch] = [c*256 + tid])
        g_qA[(size_t)c * 256 + tid] = A;
        g_qB[(size_t)c * 256 + tid] = Bv;
    }
    __syncthreads();
    if (tid < NMEM) {
        float A = 1.0f, Bv = 0.0f;
#pragma unroll
        for (int qq = 0; qq < 4; qq++) {
            float a = QA[qq * NMEM + tid], b = QB[qq * NMEM + tid];
            Bv = a * Bv + b;
            A *= a;
        }
        g_cA[tid * NCH + c] = A;    // channel-major for phase2
        g_cB[tid * NCH + c] = Bv;
    }
}

// =====================================================================
// Phase 2: hierarchical exclusive scan over 8192 chunk compositions.
// 64 blocks (one per channel), 256 threads, 32 chunks per thread.
// =====================================================================
#define P2_DSMEM (2 * NCH * 4)
__global__ __launch_bounds__(256) void phase2_kernel() {
    extern __shared__ float p2sm[];
    float* cAs = p2sm;           // [8192]
    float* cBs = p2sm + NCH;     // [8192]
    __shared__ float SA[256], SB[256];
    const int ch  = blockIdx.x;
    const int tid = threadIdx.x;

    for (int i = tid; i < NCH / 4; i += 256) {
        ((float4*)cAs)[i] = ((const float4*)(g_cA + (size_t)ch * NCH))[i];
        ((float4*)cBs)[i] = ((const float4*)(g_cB + (size_t)ch * NCH))[i];
    }
    __syncthreads();

    const int base = tid * 32;
    float A = 1.0f, Bv = 0.0f;
#pragma unroll
    for (int j = 0; j < 32; j++) {
        float a = cAs[base + j], b = cBs[base + j];
        Bv = a * Bv + b;
        A *= a;
    }
    SA[tid] = A; SB[tid] = Bv;
    __syncthreads();

#pragma unroll
    for (int s = 1; s < 256; s <<= 1) {
        float ta = SA[tid], tb = SB[tid];
        float pa = 1.0f, pb = 0.0f;
        if (tid >= s) { pa = SA[tid - s]; pb = SB[tid - s]; }
        __syncthreads();
        if (tid >= s) { SA[tid] = ta * pa; SB[tid] = ta * pb + tb; }
        __syncthreads();
    }

    float PB = (tid > 0) ? SB[tid - 1] : 0.0f;
#pragma unroll
    for (int j = 0; j < 32; j++) {
        g_pB[(size_t)(base + j) * NMEM + ch] = PB;
        PB = cAs[base + j] * PB + cBs[base + j];
    }
}

// =====================================================================
// Phase 3: a,b in registers; scan replay writes z DIRECTLY as bf16 hi/lo
// MMA A-tiles; GEMM2 via mma.sync bf16-split; fragment epilogue -> out.
// 256 threads = 8 warps: warp = (m-tile 0..3, n-half 0..1).
// =====================================================================
__global__ __launch_bounds__(256) void phase3_kernel(
    const float* __restrict__ B2, float* __restrict__ out) {
    __shared__ __align__(128) uint8_t ZAh[CHUNK * TSTRIDE];  // z hi [64 m][72 k]
    __shared__ __align__(128) uint8_t ZAl[CHUNK * TSTRIDE];  // z lo
    __shared__ __align__(128) uint8_t WB[9216];              // W2^T hi[32][72] then lo
    __shared__ float QAs[4 * NMEM], QBs[4 * NMEM];
    __shared__ float pBs[NMEM];
    __shared__ float b2s[OUTLEN];

    const int tid = threadIdx.x;
    const int c   = blockIdx.x;
    const size_t base = (size_t)c * CHUNK * NMEM;

    // copy pre-converted W2 tiles: 9216 B = 576 uint4 (3 trips of 256)
    for (int i = tid; i < 576; i += 256)
        ((uint4*)WB)[i] = ((const uint4*)g_W2t)[i];
    if (tid < OUTLEN) b2s[tid] = B2[tid];
    if (tid < NMEM) pBs[tid] = g_pB[(size_t)c * NMEM + tid];
    QAs[tid] = g_qA[(size_t)c * 256 + tid];
    QBs[tid] = g_qB[(size_t)c * 256 + tid];

    // load a,b for this thread's 16 rows into registers (coalesced)
    const int ch = tid & 63, q = tid >> 6;
    float ar[16], br[16];
#pragma unroll
    for (int t = 0; t < 16; t++) {
        int row = q * 16 + t;
        ar[t] = g_a[base + row * NMEM + ch];
        br[t] = g_b[base + row * NMEM + ch];
    }
    __syncthreads();   // pBs/QAs/QBs ready

    // scan replay: z -> bf16 hi/lo straight into A tiles (col = ch)
    {
        float u = pBs[ch];
#pragma unroll
        for (int j = 0; j < 3; j++)
            if (j < q) u = QAs[j * NMEM + ch] * u + QBs[j * NMEM + ch];
#pragma unroll
        for (int t = 0; t < 16; t++) {
            int row = q * 16 + t;
            __nv_bfloat16 h, l;
            bfsplit1(u, h, l);
            uint32_t off = row * TSTRIDE + ch * 2;
            *(__nv_bfloat16*)(ZAh + off) = h;
            *(__nv_bfloat16*)(ZAl + off) = l;
            u = ar[t] * u + br[t];
        }
    }
    __syncthreads();

    // GEMM2: out[64][32] = z[64][64] @ W2[64][32] via bf16-split MMA
    const int wid  = tid >> 5, lane = tid & 31;
    const int mw   = wid & 3;      // m-tile: rows 16*mw..+15
    const int nh   = wid >> 2;     // n-half: n-tiles 2*nh..2*nh+1

    uint32_t AhF[4][4], AlF[4][4];
    {
        uint32_t zh = smem_u32(ZAh);
        uint32_t zl = smem_u32(ZAl);
        uint32_t arow  = mw * 16 + (lane & 15);
        uint32_t acol8 = (lane >> 4) << 3;
#pragma unroll
        for (int kk = 0; kk < 4; kk++) {
            uint32_t o = arow * TSTRIDE + (kk * 16 + acol8) * 2;
            ldsm_x4(AhF[kk], zh + o);
            ldsm_x4(AlF[kk], zl + o);
        }
    }

    float acc[2][4];
#pragma unroll
    for (int j = 0; j < 2; j++)
#pragma unroll
        for (int p = 0; p < 4; p++) acc[j][p] = 0.0f;

    const uint32_t brow7 = lane & 7;
    const uint32_t bcol8 = (lane >> 3) << 3;
    const uint32_t wbh = smem_u32(WB);
    const uint32_t wbl = wbh + 4608;
#pragma unroll
    for (int j = 0; j < 2; j++) {
        int jn = nh * 2 + j;                   // n-tile 0..3
#pragma unroll
        for (int kk2 = 0; kk2 < 2; kk2++) {
            uint32_t o = (8 * jn + brow7) * TSTRIDE + (kk2 * 32 + bcol8) * 2;
            uint32_t Bhf[4], Blf[4];
            ldsm_x4(Bhf, wbh + o);
            ldsm_x4(Blf, wbl + o);
#pragma unroll
            for (int sh = 0; sh < 2; sh++) {
                int s = kk2 * 2 + sh;
                mma16816(acc[j], AhF[s], Bhf[sh * 2], Bhf[sh * 2 + 1]);  // zh*Wh
                mma16816(acc[j], AhF[s], Blf[sh * 2], Blf[sh * 2 + 1]);  // zh*Wl
                mma16816(acc[j], AlF[s], Bhf[sh * 2], Bhf[sh * 2 + 1]);  // zl*Wh
            }
        }
    }

    // epilogue: bias + store fragments to out
    {
        int r0  = mw * 16 + (lane >> 2);
        int c0  = (lane & 3) * 2;
        size_t rbase = (size_t)c * CHUNK;
#pragma unroll
        for (int j = 0; j < 2; j++) {
            int col = 8 * (nh * 2 + j) + c0;
            float ba = b2s[col], bb = b2s[col + 1];
            float2 o0 = make_float2(acc[j][0] + ba, acc[j][1] + bb);
            float2 o1 = make_float2(acc[j][2] + ba, acc[j][3] + bb);
            *(float2*)&out[(rbase + r0) * OUTLEN + col]     = o0;
            *(float2*)&out[(rbase + r0 + 8) * OUTLEN + col] = o1;
        }
    }
}

// =====================================================================
extern "C" void kernel_launch(void* const* d_in, const int* in_sizes, int n_in,
                              void* d_out, int out_size) {
    const float* x  = (const float*)d_in[0];   // [T, 64]
    const float* W1 = (const float*)d_in[1];   // [64, 128]
    const float* B1 = (const float*)d_in[2];   // [1, 128]
    const float* W2 = (const float*)d_in[3];   // [64, 32]
    const float* B2 = (const float*)d_in[4];   // [1, 32]
    float* out = (float*)d_out;                // [T, 32]

    cudaFuncSetAttribute(phase1_kernel, cudaFuncAttributeMaxDynamicSharedMemorySize, P1_DSMEM);
    cudaFuncSetAttribute(phase2_kernel, cudaFuncAttributeMaxDynamicSharedMemorySize, P2_DSMEM);

    convW_kernel<<<1, 512>>>(W1, W2);
    phase1_kernel<<<NCH, 256, P1_DSMEM>>>(x, B1);
    phase2_kernel<<<64, 256, P2_DSMEM>>>();
    phase3_kernel<<<NCH, 256>>>(B2, out);
}